// round 1
// baseline (speedup 1.0000x reference)
#include <cuda_runtime.h>
#include <cstdint>

// Problem constants
#define BTOT 7200      // bs*nq = 8*900
#define EDIM 256       // embed dim = GEMM K
#define DDYN 64
#define N1   32768     // 2*E*D  (pre_dynamic out dim)
#define N2   16384     // E*D    (aft_dynamic out dim)
#define QPAD 260       // Q smem row stride (conflict-free: 260 % 32 == 4)
#define BROW 36        // B smem row stride (36 % 32 == 4)

// Inter-kernel scratch (allocation-free rule: __device__ globals)
__device__ float g_f1n[BTOT * DDYN];
__device__ float g_f2n[BTOT * EDIM];

__device__ __forceinline__ uint32_t to_tf32(float x) {
    uint32_t r;
    asm("cvt.rna.tf32.f32 %0, %1;" : "=r"(r) : "f"(x));
    return r;
}

__device__ __forceinline__ void mma_tf32(float* c, const uint32_t* a, uint32_t b0, uint32_t b1) {
    asm volatile(
        "mma.sync.aligned.m16n8k8.row.col.f32.tf32.tf32.f32 "
        "{%0,%1,%2,%3}, {%4,%5,%6,%7}, {%8,%9}, {%0,%1,%2,%3};"
        : "+f"(c[0]), "+f"(c[1]), "+f"(c[2]), "+f"(c[3])
        : "r"(a[0]), "r"(a[1]), "r"(a[2]), "r"(a[3]), "r"(b0), "r"(b1));
}

__device__ __forceinline__ void cp16(void* s, const void* g) {
    uint32_t sa = (uint32_t)__cvta_generic_to_shared(s);
    asm volatile("cp.async.cg.shared.global [%0], [%1], 16;" :: "r"(sa), "l"(g));
}

// C[64 x 128] = Qs(64 x 256, tf32) @ W[p0 .. p0+128)^T, K = 256.
// 8 warps in a 2(m) x 4(n) grid, each computing 32x32 via m16n8k8 tf32 MMA.
// W streamed through a cp.async double buffer, 8 K-chunks of 32.
__device__ __forceinline__ void gemm_tile(
    const uint32_t* __restrict__ Qs, float* __restrict__ Bs,
    const float* __restrict__ W, int p0,
    int wm, int wn, int gID, int t4, int tid,
    float cacc[2][4][4])
{
#pragma unroll
    for (int mi = 0; mi < 2; mi++)
#pragma unroll
        for (int ni = 0; ni < 4; ni++)
#pragma unroll
            for (int e = 0; e < 4; e++) cacc[mi][ni][e] = 0.f;

    // prefetch K-chunk 0 into buffer 0
#pragma unroll
    for (int it = 0; it < 4; it++) {
        int i = tid + it * 256;
        int row = i >> 3, c4 = i & 7;
        cp16(&Bs[row * BROW + c4 * 4], &W[(p0 + row) * EDIM + c4 * 4]);
    }
    asm volatile("cp.async.commit_group;" ::: "memory");

    for (int ch = 0; ch < 8; ch++) {
        if (ch < 7) {
            float* Bn = Bs + ((ch + 1) & 1) * 128 * BROW;
#pragma unroll
            for (int it = 0; it < 4; it++) {
                int i = tid + it * 256;
                int row = i >> 3, c4 = i & 7;
                cp16(&Bn[row * BROW + c4 * 4], &W[(p0 + row) * EDIM + (ch + 1) * 32 + c4 * 4]);
            }
            asm volatile("cp.async.commit_group;" ::: "memory");
            asm volatile("cp.async.wait_group 1;" ::: "memory");
        } else {
            asm volatile("cp.async.wait_group 0;" ::: "memory");
        }
        __syncthreads();
        const float* Bb = Bs + (ch & 1) * 128 * BROW;
#pragma unroll
        for (int ks = 0; ks < 4; ks++) {
            const int kg = ch * 32 + ks * 8;
            uint32_t a[2][4];
#pragma unroll
            for (int mi = 0; mi < 2; mi++) {
                const uint32_t* q0 = Qs + (wm * 32 + mi * 16 + gID) * QPAD + kg;
                const uint32_t* q1 = q0 + 8 * QPAD;
                a[mi][0] = q0[t4];
                a[mi][1] = q1[t4];
                a[mi][2] = q0[t4 + 4];
                a[mi][3] = q1[t4 + 4];
            }
#pragma unroll
            for (int ni = 0; ni < 4; ni++) {
                const float* bp = Bb + (wn * 32 + ni * 8 + gID) * BROW + ks * 8;
                uint32_t b0 = to_tf32(bp[t4]);
                uint32_t b1 = to_tf32(bp[t4 + 4]);
                mma_tf32(cacc[0][ni], a[0], b0, b1);
                mma_tf32(cacc[1][ni], a[1], b0, b1);
            }
        }
        __syncthreads();
    }
}

// Stage 1: f1[b,d] = sum_k feats[b,k] * (Q@W_pre^T + b_pre)[b, k*64+d]; LN(D) + relu.
__global__ void __launch_bounds__(256, 1) k1_kernel(
    const float* __restrict__ q, const float* __restrict__ feats,
    const float* __restrict__ Wpre, const float* __restrict__ bpre,
    const float* __restrict__ g1, const float* __restrict__ be1)
{
    extern __shared__ unsigned char sraw[];
    uint32_t* Qs = (uint32_t*)sraw;                                        // 64 x QPAD
    float* Bs  = (float*)(sraw + 64 * QPAD * 4);                           // 2 x 128 x BROW
    float* f1a = (float*)(sraw + 64 * QPAD * 4 + 2 * 128 * BROW * 4);      // 64 x 65
    float* fsm = f1a + 64 * 65;                                            // 64 x 2
    float* bsm = fsm + 128;                                                // 128

    const int tid = threadIdx.x;
    const int m0 = blockIdx.x * 64;
    const int warp = tid >> 5, lane = tid & 31;
    const int wm = warp >> 2, wn = warp & 3;
    const int gID = lane >> 2, t4 = lane & 3;

    for (int i = tid; i < 64 * EDIM; i += 256) {
        int r = i >> 8, c = i & 255;
        float v = (m0 + r < BTOT) ? q[(m0 + r) * EDIM + c] : 0.f;
        Qs[r * QPAD + c] = to_tf32(v);
    }
    for (int i = tid; i < 64 * 65; i += 256) f1a[i] = 0.f;
    __syncthreads();

    float cacc[2][4][4];
    for (int p0 = 0; p0 < N1; p0 += 128) {
        gemm_tile(Qs, Bs, Wpre, p0, wm, wn, gID, t4, tid, cacc);
        if (tid < 128) {
            int r = tid >> 1, ks = tid & 1;
            int b = m0 + r;
            fsm[tid] = (b < BTOT) ? feats[b * 512 + (p0 >> 6) + ks] : 0.f;
            bsm[tid] = bpre[p0 + tid];
        }
        __syncthreads();
#pragma unroll
        for (int mi = 0; mi < 2; mi++) {
            int row0 = wm * 32 + mi * 16 + gID;
#pragma unroll
            for (int ni = 0; ni < 4; ni++) {
                int col0 = wn * 32 + ni * 8 + t4 * 2;
#pragma unroll
                for (int e = 0; e < 4; e++) {
                    int row = row0 + ((e >> 1) << 3);
                    int col = col0 + (e & 1);
                    float val = cacc[mi][ni][e] + bsm[col];
                    atomicAdd(&f1a[row * 65 + (col & 63)], fsm[row * 2 + (col >> 6)] * val);
                }
            }
        }
        __syncthreads();
    }

    if (tid < 64) {
        int b = m0 + tid;
        if (b < BTOT) {
            float s = 0.f, s2 = 0.f;
#pragma unroll
            for (int d = 0; d < 64; d++) { float v = f1a[tid * 65 + d]; s += v; s2 += v * v; }
            float mu = s * (1.f / 64.f);
            float var = s2 * (1.f / 64.f) - mu * mu;
            float inv = rsqrtf(var + 1e-5f);
            for (int d = 0; d < 64; d++) {
                float v = (f1a[tid * 65 + d] - mu) * inv * g1[d] + be1[d];
                g_f1n[b * 64 + d] = fmaxf(v, 0.f);
            }
        }
    }
}

// Stage 2: f2[b,e] = sum_d f1n[b,d] * (Q@W_aft^T + b_aft)[b, d*256+e]; LN(E) + relu.
__global__ void __launch_bounds__(256, 1) k2_kernel(
    const float* __restrict__ q, const float* __restrict__ Waft, const float* __restrict__ baft,
    const float* __restrict__ g2, const float* __restrict__ be2)
{
    extern __shared__ unsigned char sraw[];
    uint32_t* Qs = (uint32_t*)sraw;                                        // 64 x QPAD
    float* Bs   = (float*)(sraw + 64 * QPAD * 4);                          // 2 x 128 x BROW
    float* f1sm = (float*)(sraw + 64 * QPAD * 4 + 2 * 128 * BROW * 4);     // 64 x 68
    float* f2a  = f1sm + 64 * 68;                                          // 64 x 260
    float* bsm  = f2a + 64 * 260;                                          // 128

    const int tid = threadIdx.x;
    const int m0 = blockIdx.x * 64;
    const int warp = tid >> 5, lane = tid & 31;
    const int wm = warp >> 2, wn = warp & 3;
    const int gID = lane >> 2, t4 = lane & 3;

    for (int i = tid; i < 64 * EDIM; i += 256) {
        int r = i >> 8, c = i & 255;
        float v = (m0 + r < BTOT) ? q[(m0 + r) * EDIM + c] : 0.f;
        Qs[r * QPAD + c] = to_tf32(v);
    }
    for (int i = tid; i < 64 * 64; i += 256) {
        int r = i >> 6, d = i & 63;
        int b = m0 + r;
        f1sm[r * 68 + d] = (b < BTOT) ? g_f1n[b * 64 + d] : 0.f;
    }
    for (int i = tid; i < 64 * 260; i += 256) f2a[i] = 0.f;
    __syncthreads();

    float cacc[2][4][4];
    for (int p0 = 0; p0 < N2; p0 += 128) {
        gemm_tile(Qs, Bs, Waft, p0, wm, wn, gID, t4, tid, cacc);
        if (tid < 128) bsm[tid] = baft[p0 + tid];
        __syncthreads();
        const int dIdx = p0 >> 8;
        const int e0 = p0 & 255;
#pragma unroll
        for (int mi = 0; mi < 2; mi++) {
            int row0 = wm * 32 + mi * 16 + gID;
#pragma unroll
            for (int ni = 0; ni < 4; ni++) {
                int col0 = wn * 32 + ni * 8 + t4 * 2;
#pragma unroll
                for (int e = 0; e < 4; e++) {
                    int row = row0 + ((e >> 1) << 3);
                    int col = col0 + (e & 1);
                    float val = cacc[mi][ni][e] + bsm[col];
                    // unique (row, e0+col) owner per thread -> race-free +=
                    f2a[row * 260 + e0 + col] += f1sm[row * 68 + dIdx] * val;
                }
            }
        }
        __syncthreads();
    }

    if (tid < 64) {
        int b = m0 + tid;
        if (b < BTOT) {
            float s = 0.f, s2 = 0.f;
            for (int e = 0; e < 256; e++) { float v = f2a[tid * 260 + e]; s += v; s2 += v * v; }
            float mu = s * (1.f / 256.f);
            float var = s2 * (1.f / 256.f) - mu * mu;
            float inv = rsqrtf(var + 1e-5f);
            for (int e = 0; e < 256; e++) {
                float v = (f2a[tid * 260 + e] - mu) * inv * g2[e] + be2[e];
                g_f2n[b * 256 + e] = fmaxf(v, 0.f);
            }
        }
    }
}

// Stage 3: out = relu(LN(f2n @ W_out^T + b_out)).  (reshape(nq,bs,E) is a
// pure relabel of contiguous memory -> row order unchanged.)
__global__ void __launch_bounds__(256, 1) k3_kernel(
    const float* __restrict__ Wout, const float* __restrict__ bout,
    const float* __restrict__ g3, const float* __restrict__ be3,
    float* __restrict__ out)
{
    extern __shared__ unsigned char sraw[];
    uint32_t* Qs = (uint32_t*)sraw;                                        // 64 x QPAD
    float* Bs  = (float*)(sraw + 64 * QPAD * 4);                           // 2 x 128 x BROW
    float* f3a = (float*)(sraw + 64 * QPAD * 4 + 2 * 128 * BROW * 4);      // 64 x 260

    const int tid = threadIdx.x;
    const int m0 = blockIdx.x * 64;
    const int warp = tid >> 5, lane = tid & 31;
    const int wm = warp >> 2, wn = warp & 3;
    const int gID = lane >> 2, t4 = lane & 3;

    for (int i = tid; i < 64 * EDIM; i += 256) {
        int r = i >> 8, c = i & 255;
        float v = (m0 + r < BTOT) ? g_f2n[(m0 + r) * EDIM + c] : 0.f;
        Qs[r * QPAD + c] = to_tf32(v);
    }
    __syncthreads();

    float cacc[2][4][4];
    for (int p0 = 0; p0 < 256; p0 += 128) {
        gemm_tile(Qs, Bs, Wout, p0, wm, wn, gID, t4, tid, cacc);
#pragma unroll
        for (int mi = 0; mi < 2; mi++) {
            int row0 = wm * 32 + mi * 16 + gID;
#pragma unroll
            for (int ni = 0; ni < 4; ni++) {
                int col0 = wn * 32 + ni * 8 + t4 * 2;
#pragma unroll
                for (int e = 0; e < 4; e++) {
                    int row = row0 + ((e >> 1) << 3);
                    int col = col0 + (e & 1);
                    f3a[row * 260 + p0 + col] = cacc[mi][ni][e] + bout[p0 + col];
                }
            }
        }
    }
    __syncthreads();

    if (tid < 64) {
        int b = m0 + tid;
        if (b < BTOT) {
            float s = 0.f, s2 = 0.f;
            for (int e = 0; e < 256; e++) { float v = f3a[tid * 260 + e]; s += v; s2 += v * v; }
            float mu = s * (1.f / 256.f);
            float var = s2 * (1.f / 256.f) - mu * mu;
            float inv = rsqrtf(var + 1e-5f);
            for (int e = 0; e < 256; e++) {
                float v = (f3a[tid * 260 + e] - mu) * inv * g3[e] + be3[e];
                out[b * 256 + e] = fmaxf(v, 0.f);
            }
        }
    }
}

extern "C" void kernel_launch(void* const* d_in, const int* in_sizes, int n_in,
                              void* d_out, int out_size)
{
    const float* q     = (const float*)d_in[0];
    const float* feats = (const float*)d_in[1];
    const float* Wpre  = (const float*)d_in[2];
    const float* bpre  = (const float*)d_in[3];
    const float* Waft  = (const float*)d_in[4];
    const float* baft  = (const float*)d_in[5];
    const float* Wout  = (const float*)d_in[6];
    const float* bout  = (const float*)d_in[7];
    const float* g1  = (const float*)d_in[8];
    const float* be1 = (const float*)d_in[9];
    const float* g2  = (const float*)d_in[10];
    const float* be2 = (const float*)d_in[11];
    const float* g3  = (const float*)d_in[12];
    const float* be3 = (const float*)d_in[13];
    float* out = (float*)d_out;

    const int SM1 = 64 * QPAD * 4 + 2 * 128 * BROW * 4 + 64 * 65 * 4 + 128 * 4 + 128 * 4;
    const int SM2 = 64 * QPAD * 4 + 2 * 128 * BROW * 4 + 64 * 68 * 4 + 64 * 260 * 4 + 128 * 4;
    const int SM3 = 64 * QPAD * 4 + 2 * 128 * BROW * 4 + 64 * 260 * 4;

    cudaFuncSetAttribute(k1_kernel, cudaFuncAttributeMaxDynamicSharedMemorySize, SM1);
    cudaFuncSetAttribute(k2_kernel, cudaFuncAttributeMaxDynamicSharedMemorySize, SM2);
    cudaFuncSetAttribute(k3_kernel, cudaFuncAttributeMaxDynamicSharedMemorySize, SM3);

    dim3 grid(113), blk(256);  // ceil(7200/64) = 113
    k1_kernel<<<grid, blk, SM1>>>(q, feats, Wpre, bpre, g1, be1);
    k2_kernel<<<grid, blk, SM2>>>(q, Waft, baft, g2, be2);
    k3_kernel<<<grid, blk, SM3>>>(Wout, bout, g3, be3, out);
}

// round 2
// speedup vs baseline: 1.7501x; 1.7501x over previous
#include <cuda_runtime.h>
#include <cstdint>

// Problem constants
#define BTOT 7200      // bs*nq
#define EDIM 256       // GEMM K
#define N1   32768     // 2*E*D
#define N2   16384     // E*D
#define NS1  4         // k1 N-split
#define CH   16        // K-chunk
#define NCH  16        // chunks per K=256
#define BP   20        // B smem row pad (words): 20*gid mod 32 distinct mults of 4
#define BUFW (128*BP)  // words per B stage

// Inter-kernel scratch (__device__ globals: allocation-free rule)
__device__ float g_f1p[NS1 * BTOT * 64];   // k1 partials per N-split
__device__ float g_f1n[BTOT * 64];         // LN1 output
__device__ float g_f2p[2 * BTOT * 256];    // k2 partials per d-split
__device__ float g_f2n[BTOT * 256];        // LN2 output

__device__ __forceinline__ uint32_t to_tf32(float x) {
    uint32_t r;
    asm("cvt.rna.tf32.f32 %0, %1;" : "=r"(r) : "f"(x));
    return r;
}

__device__ __forceinline__ void mma_tf32(float* c, const uint32_t* a, uint32_t b0, uint32_t b1) {
    asm volatile(
        "mma.sync.aligned.m16n8k8.row.col.f32.tf32.tf32.f32 "
        "{%0,%1,%2,%3}, {%4,%5,%6,%7}, {%8,%9}, {%0,%1,%2,%3};"
        : "+f"(c[0]), "+f"(c[1]), "+f"(c[2]), "+f"(c[3])
        : "r"(a[0]), "r"(a[1]), "r"(a[2]), "r"(a[3]), "r"(b0), "r"(b1));
}

__device__ __forceinline__ void cp16(void* s, const void* g) {
    uint32_t sa = (uint32_t)__cvta_generic_to_shared(s);
    asm volatile("cp.async.cg.shared.global [%0], [%1], 16;" :: "r"(sa), "l"(g));
}

// Issue cp.async for one 128-row x 16-col chunk of W into stage buffer Bb.
__device__ __forceinline__ void issue_chunk(float* Bb, const float* __restrict__ W,
                                            int p0, int ch, int tid) {
#pragma unroll
    for (int it = 0; it < 2; it++) {
        int i = tid + it * 256;
        int row = i >> 2, c4 = i & 3;
        cp16(&Bb[row * BP + c4 * 4], &W[(p0 + row) * EDIM + ch * CH + c4 * 4]);
    }
}

// cacc[64x128] = Qs(64x256 tf32, XOR-swizzled) @ W[p0..p0+128)^T.
// 3-stage cp.async ring, ONE __syncthreads per 16-K chunk.
__device__ __forceinline__ void gemm256(
    const uint32_t* __restrict__ Qs, float* __restrict__ Bs,
    const float* __restrict__ W, int p0,
    int wm, int wn, int gID, int t4, int tid,
    float cacc[2][4][4])
{
#pragma unroll
    for (int mi = 0; mi < 2; mi++)
#pragma unroll
        for (int ni = 0; ni < 4; ni++)
#pragma unroll
            for (int e = 0; e < 4; e++) cacc[mi][ni][e] = 0.f;

    __syncthreads();  // protect stage buffers from previous tile's consumers

    issue_chunk(Bs, W, p0, 0, tid);
    asm volatile("cp.async.commit_group;" ::: "memory");
    issue_chunk(Bs + BUFW, W, p0, 1, tid);
    asm volatile("cp.async.commit_group;" ::: "memory");

    for (int ch = 0; ch < NCH; ch++) {
        if (ch < NCH - 1) asm volatile("cp.async.wait_group 1;" ::: "memory");
        else              asm volatile("cp.async.wait_group 0;" ::: "memory");
        __syncthreads();
        if (ch + 2 < NCH) {
            issue_chunk(Bs + ((ch + 2) % 3) * BUFW, W, p0, ch + 2, tid);
            asm volatile("cp.async.commit_group;" ::: "memory");
        }
        const float* Bb = Bs + (ch % 3) * BUFW;
#pragma unroll
        for (int ks = 0; ks < 2; ks++) {
            const int kg = ch * CH + ks * 8;
            const int sw = gID << 2;
            const int i0 = (kg + t4) ^ sw;
            const int i1 = i0 ^ 4;
            uint32_t a[2][4];
#pragma unroll
            for (int mi = 0; mi < 2; mi++) {
                const uint32_t* q0 = Qs + (wm * 32 + mi * 16 + gID) * 256;
                a[mi][0] = q0[i0];
                a[mi][1] = q0[2048 + i0];
                a[mi][2] = q0[i1];
                a[mi][3] = q0[2048 + i1];
            }
#pragma unroll
            for (int ni = 0; ni < 4; ni++) {
                const float* bp = Bb + (wn * 32 + ni * 8 + gID) * BP + ks * 8;
                uint32_t b0 = to_tf32(bp[t4]);
                uint32_t b1 = to_tf32(bp[t4 + 4]);
                mma_tf32(cacc[0][ni], a[0], b0, b1);
                mma_tf32(cacc[1][ni], a[1], b0, b1);
            }
        }
    }
}

// Load Q block (64 rows) into swizzled tf32 smem.
__device__ __forceinline__ void load_q(uint32_t* Qs, const float* __restrict__ src,
                                       int m0, int tid) {
    for (int i = tid; i < 64 * 256; i += 256) {
        int r = i >> 8, c = i & 255;
        float v = (m0 + r < BTOT) ? src[(m0 + r) * 256 + c] : 0.f;
        Qs[r * 256 + (c ^ ((r & 7) << 2))] = to_tf32(v);
    }
}

// ---------------- Stage 1: 64 tiles of (Q@Wpre^T), contracted vs feats -------
__global__ void __launch_bounds__(256, 2) k1_kernel(
    const float* __restrict__ q, const float* __restrict__ feats,
    const float* __restrict__ Wpre, const float* __restrict__ bpre)
{
    extern __shared__ unsigned char sraw[];
    uint32_t* Qs = (uint32_t*)sraw;                 // 64x256 (65536 B)
    float* Bs  = (float*)(sraw + 65536);            // 3x128xBP (30720 B)
    float* f1a = (float*)(sraw + 96256);            // 64x65   (16640 B)

    const int tid = threadIdx.x;
    const int m0 = blockIdx.x * 64;
    const int nt0 = blockIdx.y * 64;                // tile base (of 256 total)
    const int warp = tid >> 5, lane = tid & 31;
    const int wm = warp >> 2, wn = warp & 3;
    const int gID = lane >> 2, t4 = lane & 3;
    const int h = wn >> 1;                          // feats k-slot within tile

    load_q(Qs, q, m0, tid);
    for (int i = tid; i < 64 * 65; i += 256) f1a[i] = 0.f;
    __syncthreads();

    float freg[2][4][4];
#pragma unroll
    for (int mi = 0; mi < 2; mi++)
#pragma unroll
        for (int ni = 0; ni < 4; ni++)
#pragma unroll
            for (int e = 0; e < 4; e++) freg[mi][ni][e] = 0.f;

    float cacc[2][4][4];
    for (int t = 0; t < 64; t++) {
        const int p0 = (nt0 + t) << 7;
        gemm256(Qs, Bs, Wpre, p0, wm, wn, gID, t4, tid, cacc);

        const int kf = p0 >> 6;
        float fv[2][2];
#pragma unroll
        for (int mi = 0; mi < 2; mi++)
#pragma unroll
            for (int eh = 0; eh < 2; eh++) {
                int b = m0 + wm * 32 + mi * 16 + gID + (eh << 3);
                fv[mi][eh] = (b < BTOT) ? __ldg(&feats[b * 512 + kf + h]) : 0.f;
            }
#pragma unroll
        for (int ni = 0; ni < 4; ni++) {
            int colb = wn * 32 + ni * 8 + t4 * 2;
            float b0 = __ldg(&bpre[p0 + colb]);
            float b1 = __ldg(&bpre[p0 + colb + 1]);
#pragma unroll
            for (int mi = 0; mi < 2; mi++)
#pragma unroll
                for (int e = 0; e < 4; e++) {
                    float bias = (e & 1) ? b1 : b0;
                    freg[mi][ni][e] += fv[mi][e >> 1] * (cacc[mi][ni][e] + bias);
                }
        }
    }

    __syncthreads();
#pragma unroll
    for (int mi = 0; mi < 2; mi++)
#pragma unroll
        for (int ni = 0; ni < 4; ni++)
#pragma unroll
            for (int e = 0; e < 4; e++) {
                int row = wm * 32 + mi * 16 + gID + ((e >> 1) << 3);
                int col = wn * 32 + ni * 8 + t4 * 2 + (e & 1);
                atomicAdd(&f1a[row * 65 + (col & 63)], freg[mi][ni][e]);  // 2-way
            }
    __syncthreads();

    float* dst = g_f1p + blockIdx.y * (BTOT * 64);
    for (int i = tid; i < 64 * 64; i += 256) {
        int r = i >> 6, d = i & 63;
        int b = m0 + r;
        if (b < BTOT) dst[b * 64 + d] = f1a[r * 65 + d];
    }
}

// ---------------- LN1: sum NS1 partials, LayerNorm(64)+relu ------------------
__global__ void __launch_bounds__(256, 4) ln1_kernel(
    const float* __restrict__ g1, const float* __restrict__ be1)
{
    const int tid = threadIdx.x;
    const int b = blockIdx.x * 64 + (tid >> 2);
    if (b >= BTOT) return;
    const int d0 = (tid & 3) * 16;
    float v[16], s = 0.f, s2 = 0.f;
#pragma unroll
    for (int i = 0; i < 16; i++) {
        int d = d0 + i;
        float x = 0.f;
#pragma unroll
        for (int sp = 0; sp < NS1; sp++) x += g_f1p[sp * (BTOT * 64) + b * 64 + d];
        v[i] = x; s += x; s2 += x * x;
    }
    s  += __shfl_xor_sync(0xffffffffu, s, 1);  s  += __shfl_xor_sync(0xffffffffu, s, 2);
    s2 += __shfl_xor_sync(0xffffffffu, s2, 1); s2 += __shfl_xor_sync(0xffffffffu, s2, 2);
    float mu = s * (1.f / 64.f);
    float inv = rsqrtf(s2 * (1.f / 64.f) - mu * mu + 1e-5f);
#pragma unroll
    for (int i = 0; i < 16; i++) {
        int d = d0 + i;
        float y = (v[i] - mu) * inv * g1[d] + be1[d];
        g_f1n[b * 64 + d] = fmaxf(y, 0.f);
    }
}

// ---------------- Stage 2: (Q@Waft^T) contracted vs f1n, reg accumulators ----
__global__ void __launch_bounds__(256, 2) k2_kernel(
    const float* __restrict__ q, const float* __restrict__ Waft,
    const float* __restrict__ baft)
{
    extern __shared__ unsigned char sraw[];
    uint32_t* Qs = (uint32_t*)sraw;                 // 65536 B
    float* Bs  = (float*)(sraw + 65536);            // 30720 B
    float* f1s = (float*)(sraw + 96256);            // 64x65 (16640 B)

    const int tid = threadIdx.x;
    const int m0 = blockIdx.x * 64;
    const int e0 = blockIdx.y << 7;                 // 0 or 128
    const int d0 = blockIdx.z << 5;                 // 0 or 32
    const int warp = tid >> 5, lane = tid & 31;
    const int wm = warp >> 2, wn = warp & 3;
    const int gID = lane >> 2, t4 = lane & 3;

    load_q(Qs, q, m0, tid);
    for (int i = tid; i < 64 * 64; i += 256) {
        int r = i >> 6, d = i & 63;
        int b = m0 + r;
        f1s[r * 65 + d] = (b < BTOT) ? g_f1n[b * 64 + d] : 0.f;
    }
    __syncthreads();

    float facc[2][4][4];
#pragma unroll
    for (int mi = 0; mi < 2; mi++)
#pragma unroll
        for (int ni = 0; ni < 4; ni++)
#pragma unroll
            for (int e = 0; e < 4; e++) facc[mi][ni][e] = 0.f;

    float cacc[2][4][4];
    for (int dt = 0; dt < 32; dt++) {
        const int d = d0 + dt;
        const int p0 = (d << 8) + e0;
        gemm256(Qs, Bs, Waft, p0, wm, wn, gID, t4, tid, cacc);

        float fv[2][2];
#pragma unroll
        for (int mi = 0; mi < 2; mi++)
#pragma unroll
            for (int eh = 0; eh < 2; eh++) {
                int r = wm * 32 + mi * 16 + gID + (eh << 3);
                fv[mi][eh] = f1s[r * 65 + d];
            }
#pragma unroll
        for (int ni = 0; ni < 4; ni++) {
            int colb = wn * 32 + ni * 8 + t4 * 2;
            float b0 = __ldg(&baft[p0 + colb]);
            float b1 = __ldg(&baft[p0 + colb + 1]);
#pragma unroll
            for (int mi = 0; mi < 2; mi++)
#pragma unroll
                for (int e = 0; e < 4; e++) {
                    float bias = (e & 1) ? b1 : b0;
                    facc[mi][ni][e] += fv[mi][e >> 1] * (cacc[mi][ni][e] + bias);
                }
        }
    }

    // (row, e0+col) unique per thread -> plain stores into d-split partial
    float* dst = g_f2p + blockIdx.z * (BTOT * 256);
#pragma unroll
    for (int mi = 0; mi < 2; mi++)
#pragma unroll
        for (int ni = 0; ni < 4; ni++)
#pragma unroll
            for (int e = 0; e < 4; e++) {
                int row = wm * 32 + mi * 16 + gID + ((e >> 1) << 3);
                int col = wn * 32 + ni * 8 + t4 * 2 + (e & 1);
                int b = m0 + row;
                if (b < BTOT) dst[b * 256 + e0 + col] = facc[mi][ni][e];
            }
}

// ---------------- LN2: sum 2 partials, LayerNorm(256)+relu -------------------
__global__ void __launch_bounds__(256, 4) ln2_kernel(
    const float* __restrict__ g2, const float* __restrict__ be2)
{
    const int tid = threadIdx.x;
    const int b = blockIdx.x * 64 + (tid >> 2);
    if (b >= BTOT) return;
    const int e0 = (tid & 3) * 64;
    float v[64], s = 0.f, s2 = 0.f;
#pragma unroll
    for (int i = 0; i < 64; i++) {
        int e = e0 + i;
        float x = g_f2p[b * 256 + e] + g_f2p[BTOT * 256 + b * 256 + e];
        v[i] = x; s += x; s2 += x * x;
    }
    s  += __shfl_xor_sync(0xffffffffu, s, 1);  s  += __shfl_xor_sync(0xffffffffu, s, 2);
    s2 += __shfl_xor_sync(0xffffffffu, s2, 1); s2 += __shfl_xor_sync(0xffffffffu, s2, 2);
    float mu = s * (1.f / 256.f);
    float inv = rsqrtf(s2 * (1.f / 256.f) - mu * mu + 1e-5f);
#pragma unroll
    for (int i = 0; i < 64; i++) {
        int e = e0 + i;
        float y = (v[i] - mu) * inv * g2[e] + be2[e];
        g_f2n[b * 256 + e] = fmaxf(y, 0.f);
    }
}

// ---------------- Stage 3: out = relu(LN(f2n @ Wout^T + bout)) ---------------
__global__ void __launch_bounds__(256, 1) k3_kernel(
    const float* __restrict__ Wout, const float* __restrict__ bout,
    const float* __restrict__ g3, const float* __restrict__ be3,
    float* __restrict__ out)
{
    extern __shared__ unsigned char sraw[];
    uint32_t* Qs = (uint32_t*)sraw;                 // 65536 B
    float* Bs  = (float*)(sraw + 65536);            // 30720 B
    float* f3a = (float*)(sraw + 96256);            // 64x260 (66560 B)

    const int tid = threadIdx.x;
    const int m0 = blockIdx.x * 64;
    const int warp = tid >> 5, lane = tid & 31;
    const int wm = warp >> 2, wn = warp & 3;
    const int gID = lane >> 2, t4 = lane & 3;

    load_q(Qs, g_f2n, m0, tid);
    __syncthreads();

    float cacc[2][4][4];
    for (int t = 0; t < 2; t++) {
        const int p0 = t << 7;
        gemm256(Qs, Bs, Wout, p0, wm, wn, gID, t4, tid, cacc);
#pragma unroll
        for (int mi = 0; mi < 2; mi++)
#pragma unroll
            for (int ni = 0; ni < 4; ni++)
#pragma unroll
                for (int e = 0; e < 4; e++) {
                    int row = wm * 32 + mi * 16 + gID + ((e >> 1) << 3);
                    int col = wn * 32 + ni * 8 + t4 * 2 + (e & 1);
                    f3a[row * 260 + p0 + col] = cacc[mi][ni][e] + __ldg(&bout[p0 + col]);
                }
    }
    __syncthreads();

    const int row = tid >> 2;
    const int b = m0 + row;
    if (b < BTOT) {
        const int e0 = (tid & 3) * 64;
        float s = 0.f, s2 = 0.f;
#pragma unroll
        for (int i = 0; i < 64; i++) {
            float x = f3a[row * 260 + e0 + i];
            s += x; s2 += x * x;
        }
        s  += __shfl_xor_sync(0xffffffffu, s, 1);  s  += __shfl_xor_sync(0xffffffffu, s, 2);
        s2 += __shfl_xor_sync(0xffffffffu, s2, 1); s2 += __shfl_xor_sync(0xffffffffu, s2, 2);
        float mu = s * (1.f / 256.f);
        float inv = rsqrtf(s2 * (1.f / 256.f) - mu * mu + 1e-5f);
#pragma unroll
        for (int i = 0; i < 64; i++) {
            int e = e0 + i;
            float y = (f3a[row * 260 + e] - mu) * inv * g3[e] + be3[e];
            out[b * 256 + e] = fmaxf(y, 0.f);
        }
    }
}

extern "C" void kernel_launch(void* const* d_in, const int* in_sizes, int n_in,
                              void* d_out, int out_size)
{
    const float* q     = (const float*)d_in[0];
    const float* feats = (const float*)d_in[1];
    const float* Wpre  = (const float*)d_in[2];
    const float* bpre  = (const float*)d_in[3];
    const float* Waft  = (const float*)d_in[4];
    const float* baft  = (const float*)d_in[5];
    const float* Wout  = (const float*)d_in[6];
    const float* bout  = (const float*)d_in[7];
    const float* g1  = (const float*)d_in[8];
    const float* be1 = (const float*)d_in[9];
    const float* g2  = (const float*)d_in[10];
    const float* be2 = (const float*)d_in[11];
    const float* g3  = (const float*)d_in[12];
    const float* be3 = (const float*)d_in[13];
    float* out = (float*)d_out;

    const int SM12 = 65536 + 30720 + 16640;          // 112896 B -> 2 CTAs/SM
    const int SM3  = 65536 + 30720 + 64 * 260 * 4;   // 162816 B

    cudaFuncSetAttribute(k1_kernel, cudaFuncAttributeMaxDynamicSharedMemorySize, SM12);
    cudaFuncSetAttribute(k2_kernel, cudaFuncAttributeMaxDynamicSharedMemorySize, SM12);
    cudaFuncSetAttribute(k3_kernel, cudaFuncAttributeMaxDynamicSharedMemorySize, SM3);

    dim3 blk(256);
    k1_kernel<<<dim3(113, NS1), blk, SM12>>>(q, feats, Wpre, bpre);
    ln1_kernel<<<dim3(113), blk>>>(g1, be1);
    k2_kernel<<<dim3(113, 2, 2), blk, SM12>>>(q, Waft, baft);
    ln2_kernel<<<dim3(113), blk>>>(g2, be2);
    k3_kernel<<<dim3(113), blk, SM3>>>(Wout, bout, g3, be3, out);
}

// round 4
// speedup vs baseline: 4.6215x; 2.6407x over previous
#include <cuda_runtime.h>
#include <cuda_fp16.h>
#include <cstdint>

// ---------------- problem constants ----------------
#define BTOT 7200      // bs*nq
#define N1   32768     // 2*E*D
#define N2   16384     // E*D
#define NS1  4         // k1 N-split

// ---------------- smem layout (bytes from dynamic base) ----------------
#define A_STRIDE 528             // 64 rows x 528B (256 fp16, stride 33 c16-units)
#define A_BYTES  33792
#define B_OFF    33792           // 3 stages x 128 rows x 80B (32 fp16, stride 5 units)
#define B_STRIDE 80
#define B_STAGE  10240
#define EP_OFF   64512           // epilogue buffer (64x65 f32 = 16640B)
#define SMEM_12  (EP_OFF + 16640)          // 81152 -> 2 CTAs/SM
#define SMEM_3   (EP_OFF + 64*260*4)       // 131072 (k3, tiny grid)

// ---------------- device scratch (allocation-free rule) ----------------
__device__ __half g_qh   [BTOT * 256];
__device__ __half g_wpreh[(size_t)N1 * 256];
__device__ __half g_wafth[(size_t)N2 * 256];
__device__ __half g_wouth[256 * 256];
__device__ float  g_f1p  [NS1 * BTOT * 64];   // k1 partials
__device__ float  g_f1n  [BTOT * 64];         // LN1 output
__device__ float  g_f2p  [2 * BTOT * 256];    // k2 partials per d-split (race-free)
__device__ __half g_f2nh [BTOT * 256];        // LN2 output (fp16, k3 A input)

// ---------------- PTX helpers ----------------
__device__ __forceinline__ void mma_f16(float* c, const uint32_t* a, uint32_t b0, uint32_t b1) {
    asm volatile(
        "mma.sync.aligned.m16n8k16.row.col.f32.f16.f16.f32 "
        "{%0,%1,%2,%3}, {%4,%5,%6,%7}, {%8,%9}, {%0,%1,%2,%3};"
        : "+f"(c[0]), "+f"(c[1]), "+f"(c[2]), "+f"(c[3])
        : "r"(a[0]), "r"(a[1]), "r"(a[2]), "r"(a[3]), "r"(b0), "r"(b1));
}

__device__ __forceinline__ void ldsm4(uint32_t& r0, uint32_t& r1, uint32_t& r2, uint32_t& r3,
                                      uint32_t addr) {
    asm volatile("ldmatrix.sync.aligned.m8n8.x4.shared.b16 {%0,%1,%2,%3}, [%4];"
        : "=r"(r0), "=r"(r1), "=r"(r2), "=r"(r3) : "r"(addr));
}

__device__ __forceinline__ void cp16z(uint32_t s, const void* g, uint32_t sz) {
    asm volatile("cp.async.cg.shared.global [%0], [%1], 16, %2;" :: "r"(s), "l"(g), "r"(sz));
}
__device__ __forceinline__ void cp16(uint32_t s, const void* g) {
    asm volatile("cp.async.cg.shared.global [%0], [%1], 16;" :: "r"(s), "l"(g));
}
#define CP_COMMIT asm volatile("cp.async.commit_group;" ::: "memory")
#define CP_WAIT0  asm volatile("cp.async.wait_group 0;" ::: "memory")
#define CP_WAIT1  asm volatile("cp.async.wait_group 1;" ::: "memory")

// ---------------- A tile load: 64 rows x 256 fp16 ----------------
__device__ __forceinline__ void load_A(uint32_t A, const __half* __restrict__ src,
                                       int m0, int tid) {
#pragma unroll
    for (int it = 0; it < 8; it++) {
        int idx = tid + it * 256;           // 0..2047
        int r = idx >> 5, c16 = idx & 31;
        uint32_t dst = A + r * A_STRIDE + c16 * 16;
        int gr = m0 + r;
        bool v = gr < BTOT;
        const __half* g = src + (v ? ((size_t)gr * 256 + c16 * 8) : 0);
        cp16z(dst, g, v ? 16u : 0u);
    }
    CP_COMMIT;
}

__device__ __forceinline__ void issue_B(uint32_t Bst, const __half* __restrict__ W,
                                        int p0, int ch, int tid) {
#pragma unroll
    for (int it = 0; it < 2; it++) {
        int idx = tid + it * 256;           // 0..511
        int row = idx >> 2, c16 = idx & 3;
        cp16(Bst + row * B_STRIDE + c16 * 16,
             W + (size_t)(p0 + row) * 256 + ch * 32 + c16 * 8);
    }
    CP_COMMIT;
}

// cacc[64x128] = A(64x256 fp16 smem) @ W[p0..p0+128)^T via m16n8k16.
__device__ __forceinline__ void gemm256h(
    uint32_t A, uint32_t B, const __half* __restrict__ W, int p0,
    uint32_t aaddr0, uint32_t aaddr1, uint32_t boff, int tid,
    float cacc[2][4][4])
{
#pragma unroll
    for (int mi = 0; mi < 2; mi++)
#pragma unroll
        for (int ni = 0; ni < 4; ni++)
#pragma unroll
            for (int e = 0; e < 4; e++) cacc[mi][ni][e] = 0.f;

    __syncthreads();  // protect stages from previous tile's consumers

    issue_B(B,           W, p0, 0, tid);
    issue_B(B + B_STAGE, W, p0, 1, tid);

    for (int ch = 0; ch < 8; ch++) {
        if (ch < 7) CP_WAIT1; else CP_WAIT0;
        __syncthreads();
        if (ch + 2 < 8) issue_B(B + ((ch + 2) % 3) * B_STAGE, W, p0, ch + 2, tid);
        const uint32_t Bst = B + (ch % 3) * B_STAGE;
#pragma unroll
        for (int ks = 0; ks < 2; ks++) {
            const uint32_t ka = (uint32_t)(ch * 4 + ks * 2) * 16;
            uint32_t a[2][4];
            ldsm4(a[0][0], a[0][1], a[0][2], a[0][3], aaddr0 + ka);
            ldsm4(a[1][0], a[1][1], a[1][2], a[1][3], aaddr1 + ka);
            uint32_t b[4][2];
            ldsm4(b[0][0], b[0][1], b[1][0], b[1][1], Bst + boff + ks * 32);
            ldsm4(b[2][0], b[2][1], b[3][0], b[3][1], Bst + boff + ks * 32 + 16 * B_STRIDE);
#pragma unroll
            for (int nf = 0; nf < 4; nf++) {
                mma_f16(cacc[0][nf], a[0], b[nf][0], b[nf][1]);
                mma_f16(cacc[1][nf], a[1], b[nf][0], b[nf][1]);
            }
        }
    }
}

__device__ __forceinline__ void frag_addrs(uint32_t A, int wm, int wn, int lane,
                                           uint32_t& aaddr0, uint32_t& aaddr1, uint32_t& boff) {
    int a_row = ((lane >> 3) & 1) * 8 + (lane & 7);
    int a_cj  = lane >> 4;
    aaddr0 = A + (uint32_t)(wm * 32 + a_row) * A_STRIDE + (uint32_t)a_cj * 16;
    aaddr1 = aaddr0 + 16 * A_STRIDE;
    int b_row = (lane >> 4) * 8 + (lane & 7);
    int b_cj  = (lane >> 3) & 1;
    boff = (uint32_t)(wn * 32 + b_row) * B_STRIDE + (uint32_t)b_cj * 16;
}

// ---------------- preround: fp32 -> fp16 ----------------
__global__ void __launch_bounds__(256, 8) preround_kernel(
    const float* __restrict__ q, const float* __restrict__ wpre,
    const float* __restrict__ waft, const float* __restrict__ wout)
{
    size_t i = (size_t)blockIdx.x * 256 + threadIdx.x;
    const size_t S1 = (size_t)N1 * 64;
    const size_t S2 = S1 + (size_t)N2 * 64;
    const size_t S3 = S2 + 256 * 64;
    const size_t S4 = S3 + (size_t)BTOT * 64;
    if (i >= S4) return;
    const float* src; __half* dst; size_t off;
    if (i < S1)      { src = wpre; dst = g_wpreh; off = i; }
    else if (i < S2) { src = waft; dst = g_wafth; off = i - S1; }
    else if (i < S3) { src = wout; dst = g_wouth; off = i - S2; }
    else             { src = q;    dst = g_qh;    off = i - S3; }
    float4 v = ((const float4*)src)[off];
    ((__half2*)dst)[off * 2]     = __floats2half2_rn(v.x, v.y);
    ((__half2*)dst)[off * 2 + 1] = __floats2half2_rn(v.z, v.w);
}

// ---------------- Stage 1 ----------------
__global__ void __launch_bounds__(256, 2) k1_kernel(
    const float* __restrict__ feats, const float* __restrict__ bpre)
{
    extern __shared__ unsigned char sm[];
    uint32_t sb = (uint32_t)__cvta_generic_to_shared(sm);
    const uint32_t A = sb, B = sb + B_OFF;
    float* f1a = (float*)(sm + EP_OFF);

    const int tid = threadIdx.x, warp = tid >> 5, lane = tid & 31;
    const int wm = warp >> 2, wn = warp & 3;
    const int gID = lane >> 2, t4 = lane & 3;
    const int m0 = blockIdx.x * 64;
    const int nt0 = blockIdx.y * 64;
    const int h = wn >> 1;

    uint32_t aaddr0, aaddr1, boff;
    frag_addrs(A, wm, wn, lane, aaddr0, aaddr1, boff);

    load_A(A, g_qh, m0, tid);
    for (int i = tid; i < 64 * 65; i += 256) f1a[i] = 0.f;
    CP_WAIT0;
    __syncthreads();

    float freg[2][4][4];
#pragma unroll
    for (int mi = 0; mi < 2; mi++)
#pragma unroll
        for (int ni = 0; ni < 4; ni++)
#pragma unroll
            for (int e = 0; e < 4; e++) freg[mi][ni][e] = 0.f;

    float cacc[2][4][4];
    for (int t = 0; t < 64; t++) {
        const int p0 = (nt0 + t) << 7;
        gemm256h(A, B, g_wpreh, p0, aaddr0, aaddr1, boff, tid, cacc);

        const int kf = p0 >> 6;
        float fv[2][2];
#pragma unroll
        for (int mi = 0; mi < 2; mi++)
#pragma unroll
            for (int eh = 0; eh < 2; eh++) {
                int b = m0 + wm * 32 + mi * 16 + gID + (eh << 3);
                fv[mi][eh] = (b < BTOT) ? __ldg(&feats[(size_t)b * 512 + kf + h]) : 0.f;
            }
#pragma unroll
        for (int ni = 0; ni < 4; ni++) {
            int colb = wn * 32 + ni * 8 + t4 * 2;
            float b0 = __ldg(&bpre[p0 + colb]);
            float b1 = __ldg(&bpre[p0 + colb + 1]);
#pragma unroll
            for (int mi = 0; mi < 2; mi++)
#pragma unroll
                for (int e = 0; e < 4; e++) {
                    float bias = (e & 1) ? b1 : b0;
                    freg[mi][ni][e] += fv[mi][e >> 1] * (cacc[mi][ni][e] + bias);
                }
        }
    }

    __syncthreads();
#pragma unroll
    for (int mi = 0; mi < 2; mi++)
#pragma unroll
        for (int ni = 0; ni < 4; ni++)
#pragma unroll
            for (int e = 0; e < 4; e++) {
                int row = wm * 32 + mi * 16 + gID + ((e >> 1) << 3);
                int col = wn * 32 + ni * 8 + t4 * 2 + (e & 1);
                atomicAdd(&f1a[row * 65 + (col & 63)], freg[mi][ni][e]);
            }
    __syncthreads();

    float* dst = g_f1p + (size_t)blockIdx.y * (BTOT * 64);
    for (int i = tid; i < 64 * 64; i += 256) {
        int r = i >> 6, d = i & 63;
        int b = m0 + r;
        if (b < BTOT) dst[(size_t)b * 64 + d] = f1a[r * 65 + d];
    }
}

// ---------------- LN1 ----------------
__global__ void __launch_bounds__(256, 8) ln1_kernel(
    const float* __restrict__ g1, const float* __restrict__ be1)
{
    int w = threadIdx.x >> 5, lane = threadIdx.x & 31;
    int b = blockIdx.x * 8 + w;
    if (b >= BTOT) return;
    int d = lane * 2;
    float v0 = 0.f, v1 = 0.f;
#pragma unroll
    for (int s = 0; s < NS1; s++) {
        float2 t = *(const float2*)(g_f1p + (size_t)s * (BTOT * 64) + (size_t)b * 64 + d);
        v0 += t.x; v1 += t.y;
    }
    float s1 = v0 + v1, s2 = v0 * v0 + v1 * v1;
#pragma unroll
    for (int o = 16; o; o >>= 1) {
        s1 += __shfl_xor_sync(0xffffffffu, s1, o);
        s2 += __shfl_xor_sync(0xffffffffu, s2, o);
    }
    float mu = s1 * (1.f / 64.f);
    float inv = rsqrtf(s2 * (1.f / 64.f) - mu * mu + 1e-5f);
    float y0 = fmaxf((v0 - mu) * inv * g1[d] + be1[d], 0.f);
    float y1 = fmaxf((v1 - mu) * inv * g1[d + 1] + be1[d + 1], 0.f);
    *(float2*)(g_f1n + (size_t)b * 64 + d) = make_float2(y0, y1);
}

// ---------------- Stage 2 ----------------
__global__ void __launch_bounds__(256, 2) k2_kernel(const float* __restrict__ baft)
{
    extern __shared__ unsigned char sm[];
    uint32_t sb = (uint32_t)__cvta_generic_to_shared(sm);
    const uint32_t A = sb, B = sb + B_OFF;
    float* f1s = (float*)(sm + EP_OFF);

    const int tid = threadIdx.x, warp = tid >> 5, lane = tid & 31;
    const int wm = warp >> 2, wn = warp & 3;
    const int gID = lane >> 2, t4 = lane & 3;
    const int m0 = blockIdx.x * 64;
    const int e0 = blockIdx.y << 7;
    const int d0 = blockIdx.z << 5;

    uint32_t aaddr0, aaddr1, boff;
    frag_addrs(A, wm, wn, lane, aaddr0, aaddr1, boff);

    load_A(A, g_qh, m0, tid);
    for (int i = tid; i < 64 * 64; i += 256) {
        int r = i >> 6, d = i & 63;
        int b = m0 + r;
        f1s[r * 65 + d] = (b < BTOT) ? g_f1n[(size_t)b * 64 + d] : 0.f;
    }
    CP_WAIT0;
    __syncthreads();

    float facc[2][4][4];
#pragma unroll
    for (int mi = 0; mi < 2; mi++)
#pragma unroll
        for (int ni = 0; ni < 4; ni++)
#pragma unroll
            for (int e = 0; e < 4; e++) facc[mi][ni][e] = 0.f;

    float cacc[2][4][4];
    for (int dt = 0; dt < 32; dt++) {
        const int d = d0 + dt;
        const int p0 = (d << 8) + e0;
        gemm256h(A, B, g_wafth, p0, aaddr0, aaddr1, boff, tid, cacc);

        float fv[2][2];
#pragma unroll
        for (int mi = 0; mi < 2; mi++)
#pragma unroll
            for (int eh = 0; eh < 2; eh++) {
                int r = wm * 32 + mi * 16 + gID + (eh << 3);
                fv[mi][eh] = f1s[r * 65 + d];
            }
#pragma unroll
        for (int ni = 0; ni < 4; ni++) {
            int colb = wn * 32 + ni * 8 + t4 * 2;
            float b0 = __ldg(&baft[p0 + colb]);
            float b1 = __ldg(&baft[p0 + colb + 1]);
#pragma unroll
            for (int mi = 0; mi < 2; mi++)
#pragma unroll
                for (int e = 0; e < 4; e++) {
                    float bias = (e & 1) ? b1 : b0;
                    facc[mi][ni][e] += fv[mi][e >> 1] * (cacc[mi][ni][e] + bias);
                }
        }
    }

    float* dst = g_f2p + (size_t)blockIdx.z * (BTOT * 256);   // race-free split buffer
#pragma unroll
    for (int mi = 0; mi < 2; mi++)
#pragma unroll
        for (int ni = 0; ni < 4; ni++)
#pragma unroll
            for (int e = 0; e < 4; e++) {
                int row = wm * 32 + mi * 16 + gID + ((e >> 1) << 3);
                int col = wn * 32 + ni * 8 + t4 * 2 + (e & 1);
                int b = m0 + row;
                if (b < BTOT) dst[(size_t)b * 256 + e0 + col] = facc[mi][ni][e];
            }
}

// ---------------- LN2 -> fp16 ----------------
__global__ void __launch_bounds__(256, 8) ln2_kernel(
    const float* __restrict__ g2, const float* __restrict__ be2)
{
    int w = threadIdx.x >> 5, lane = threadIdx.x & 31;
    int b = blockIdx.x * 8 + w;
    if (b >= BTOT) return;
    float v[8], s1 = 0.f, s2 = 0.f;
#pragma unroll
    for (int i = 0; i < 8; i++) {
        float x = g_f2p[(size_t)b * 256 + i * 32 + lane]
                + g_f2p[(size_t)BTOT * 256 + (size_t)b * 256 + i * 32 + lane];
        v[i] = x; s1 += x; s2 += x * x;
    }
#pragma unroll
    for (int o = 16; o; o >>= 1) {
        s1 += __shfl_xor_sync(0xffffffffu, s1, o);
        s2 += __shfl_xor_sync(0xffffffffu, s2, o);
    }
    float mu = s1 * (1.f / 256.f);
    float inv = rsqrtf(s2 * (1.f / 256.f) - mu * mu + 1e-5f);
#pragma unroll
    for (int i = 0; i < 8; i++) {
        int e = i * 32 + lane;
        float y = fmaxf((v[i] - mu) * inv * g2[e] + be2[e], 0.f);
        g_f2nh[(size_t)b * 256 + e] = __float2half_rn(y);
    }
}

// ---------------- Stage 3 + LN3 ----------------
__global__ void __launch_bounds__(256, 1) k3_kernel(
    const float* __restrict__ bout,
    const float* __restrict__ g3, const float* __restrict__ be3,
    float* __restrict__ out)
{
    extern __shared__ unsigned char sm[];
    uint32_t sb = (uint32_t)__cvta_generic_to_shared(sm);
    const uint32_t A = sb, B = sb + B_OFF;
    float* f3a = (float*)(sm + EP_OFF);

    const int tid = threadIdx.x, warp = tid >> 5, lane = tid & 31;
    const int wm = warp >> 2, wn = warp & 3;
    const int gID = lane >> 2, t4 = lane & 3;
    const int m0 = blockIdx.x * 64;

    uint32_t aaddr0, aaddr1, boff;
    frag_addrs(A, wm, wn, lane, aaddr0, aaddr1, boff);

    load_A(A, g_f2nh, m0, tid);
    CP_WAIT0;
    __syncthreads();

    float cacc[2][4][4];
    for (int t = 0; t < 2; t++) {
        const int p0 = t << 7;
        gemm256h(A, B, g_wouth, p0, aaddr0, aaddr1, boff, tid, cacc);
#pragma unroll
        for (int mi = 0; mi < 2; mi++)
#pragma unroll
            for (int ni = 0; ni < 4; ni++)
#pragma unroll
                for (int e = 0; e < 4; e++) {
                    int row = wm * 32 + mi * 16 + gID + ((e >> 1) << 3);
                    int col = wn * 32 + ni * 8 + t4 * 2 + (e & 1);
                    f3a[row * 260 + p0 + col] = cacc[mi][ni][e] + __ldg(&bout[p0 + col]);
                }
    }
    __syncthreads();

    const int row = tid >> 2;
    const int b = m0 + row;
    if (b < BTOT) {
        const int e0 = (tid & 3) * 64;
        float s1 = 0.f, s2 = 0.f;
#pragma unroll
        for (int i = 0; i < 64; i++) {
            float x = f3a[row * 260 + e0 + i];
            s1 += x; s2 += x * x;
        }
        s1 += __shfl_xor_sync(0xffffffffu, s1, 1); s1 += __shfl_xor_sync(0xffffffffu, s1, 2);
        s2 += __shfl_xor_sync(0xffffffffu, s2, 1); s2 += __shfl_xor_sync(0xffffffffu, s2, 2);
        float mu = s1 * (1.f / 256.f);
        float inv = rsqrtf(s2 * (1.f / 256.f) - mu * mu + 1e-5f);
#pragma unroll
        for (int i = 0; i < 64; i++) {
            int e = e0 + i;
            float y = (f3a[row * 260 + e] - mu) * inv * g3[e] + be3[e];
            out[(size_t)b * 256 + e] = fmaxf(y, 0.f);
        }
    }
}

// ---------------- host launch ----------------
extern "C" void kernel_launch(void* const* d_in, const int* in_sizes, int n_in,
                              void* d_out, int out_size)
{
    const float* q     = (const float*)d_in[0];
    const float* feats = (const float*)d_in[1];
    const float* Wpre  = (const float*)d_in[2];
    const float* bpre  = (const float*)d_in[3];
    const float* Waft  = (const float*)d_in[4];
    const float* baft  = (const float*)d_in[5];
    const float* Wout  = (const float*)d_in[6];
    const float* bout  = (const float*)d_in[7];
    const float* g1  = (const float*)d_in[8];
    const float* be1 = (const float*)d_in[9];
    const float* g2  = (const float*)d_in[10];
    const float* be2 = (const float*)d_in[11];
    const float* g3  = (const float*)d_in[12];
    const float* be3 = (const float*)d_in[13];
    float* out = (float*)d_out;

    cudaFuncSetAttribute(k1_kernel, cudaFuncAttributeMaxDynamicSharedMemorySize, SMEM_12);
    cudaFuncSetAttribute(k2_kernel, cudaFuncAttributeMaxDynamicSharedMemorySize, SMEM_12);
    cudaFuncSetAttribute(k3_kernel, cudaFuncAttributeMaxDynamicSharedMemorySize, SMEM_3);

    const size_t nf4 = (size_t)N1 * 64 + (size_t)N2 * 64 + 256 * 64 + (size_t)BTOT * 64;
    int pr_blocks = (int)((nf4 + 255) / 256);

    dim3 blk(256);
    preround_kernel<<<pr_blocks, blk>>>(q, Wpre, Waft, Wout);
    k1_kernel<<<dim3(113, NS1), blk, SMEM_12>>>(feats, bpre);
    ln1_kernel<<<dim3(900), blk>>>(g1, be1);
    k2_kernel<<<dim3(113, 2, 2), blk, SMEM_12>>>(baft);
    ln2_kernel<<<dim3(900), blk>>>(g2, be2);
    k3_kernel<<<dim3(113), blk, SMEM_3>>>(bout, g3, be3, out);
}